// round 16
// baseline (speedup 1.0000x reference)
#include <cuda_runtime.h>
#include <cuda_bf16.h>
#include <cstdint>

#define BB   4
#define SS   1024
#define HID  1024
#define NH   16
#define HD   64
#define MTOT (BB*SS)

// ---------------- scratch ----------------
__device__ __nv_bfloat16 g_bx1[MTOT*HID];
__device__ __nv_bfloat16 g_bx2[MTOT*HID];
__device__ __nv_bfloat16 g_bw [4*HID*HID];      // Wq,Wk,Wv,Wo (bf16, contiguous)
__device__ __nv_bfloat16 g_bq [MTOT*HID];
__device__ __nv_bfloat16 g_bkv[MTOT*2*HID];     // COMPACTED [K | V] rows, stride 2048
__device__ __nv_bfloat16 g_bao[MTOT*HID];
__device__ __nv_bfloat16 g_by [MTOT*HID];       // y = out + bo + x_cls (bf16)
__device__ float         g_part[64*BB*HID];
__device__ int           g_idx [BB*SS];
__device__ float         g_amask[BB*SS];
__device__ int           g_cnt [BB];

// ---------------- helpers ----------------
__device__ __forceinline__ uint32_t f2bf2(float lo, float hi){
    uint32_t r; asm("cvt.rn.bf16x2.f32 %0, %1, %2;" : "=r"(r) : "f"(hi), "f"(lo));
    return r;
}
__device__ __forceinline__ float ex2f(float x){
    float y; asm("ex2.approx.ftz.f32 %0, %1;" : "=f"(y) : "f"(x)); return y;
}
__device__ __forceinline__ void mma_bf16(float* d,
    const uint32_t* a, uint32_t b0, uint32_t b1)
{
    asm volatile(
        "mma.sync.aligned.m16n8k16.row.col.f32.bf16.bf16.f32 "
        "{%0,%1,%2,%3}, {%4,%5,%6,%7}, {%8,%9}, {%0,%1,%2,%3};"
        : "+f"(d[0]), "+f"(d[1]), "+f"(d[2]), "+f"(d[3])
        : "r"(a[0]), "r"(a[1]), "r"(a[2]), "r"(a[3]), "r"(b0), "r"(b1));
}
__device__ __forceinline__ void ldsm_x4(uint32_t* r, uint32_t a){
    asm volatile("ldmatrix.sync.aligned.m8n8.x4.shared.b16 {%0,%1,%2,%3}, [%4];"
                 : "=r"(r[0]), "=r"(r[1]), "=r"(r[2]), "=r"(r[3]) : "r"(a));
}
__device__ __forceinline__ void ldsm_x4t(uint32_t* r, uint32_t a){
    asm volatile("ldmatrix.sync.aligned.m8n8.x4.trans.shared.b16 {%0,%1,%2,%3}, [%4];"
                 : "=r"(r[0]), "=r"(r[1]), "=r"(r[2]), "=r"(r[3]) : "r"(a));
}
__device__ __forceinline__ void cp16(uint32_t dst, const void* src){
    asm volatile("cp.async.cg.shared.global [%0], [%1], 16;" :: "r"(dst), "l"(src));
}
#define CP_COMMIT asm volatile("cp.async.commit_group;" ::: "memory")
#define CP_WAIT1  asm volatile("cp.async.wait_group 1;" ::: "memory")

// =============================================================================
// merged conversions: grid (4096, 6). y=0: x1, y=1: x2, y=2..5: Wq..Wo (1024 blk)
// =============================================================================
__global__ __launch_bounds__(256) void conv_all(
    const float* __restrict__ x1, const float* __restrict__ x2,
    const float* __restrict__ w0, const float* __restrict__ w1,
    const float* __restrict__ w2, const float* __restrict__ w3,
    __nv_bfloat16* __restrict__ dx1, __nv_bfloat16* __restrict__ dx2,
    __nv_bfloat16* __restrict__ dw)
{
    const int seg = blockIdx.y;
    if (seg >= 2 && blockIdx.x >= 1024) return;
    const float* s;
    __nv_bfloat16* d;
    switch (seg) {
        case 0: s = x1; d = dx1; break;
        case 1: s = x2; d = dx2; break;
        default:
            s = seg == 2 ? w0 : seg == 3 ? w1 : seg == 4 ? w2 : w3;
            d = dw + (size_t)(seg - 2) * HID * HID;
    }
    int i = (blockIdx.x * 256 + threadIdx.x) * 4;
    float4 v = *(const float4*)(s + i);
    *(uint2*)(d + i) = make_uint2(f2bf2(v.x, v.y), f2bf2(v.z, v.w));
}

// =============================================================================
// mask compaction: kept key indices per batch, padded to 128-multiple.
// =============================================================================
__global__ __launch_bounds__(256) void compact_mask(const int* __restrict__ mask)
{
    const int b = blockIdx.x;
    const int tid = threadIdx.x, lane = tid & 31, wid = tid >> 5;
    __shared__ int wsum[8];

    int m[4], cnt = 0;
    const int base = b * SS + tid * 4;
#pragma unroll
    for (int i = 0; i < 4; ++i) { m[i] = mask[base + i]; cnt += (m[i] != 0); }

    int pre = cnt;
#pragma unroll
    for (int off = 1; off < 32; off <<= 1) {
        int v = __shfl_up_sync(0xffffffffu, pre, off);
        if (lane >= off) pre += v;
    }
    if (lane == 31) wsum[wid] = pre;
    __syncthreads();

    int wbase = 0;
#pragma unroll
    for (int w = 0; w < 8; ++w) if (w < wid) wbase += wsum[w];
    int pos = wbase + pre - cnt;

#pragma unroll
    for (int i = 0; i < 4; ++i) {
        if (m[i]) {
            g_idx[b * SS + pos]   = tid * 4 + i;
            g_amask[b * SS + pos] = 0.f;
            ++pos;
        }
    }

    int total = 0;
#pragma unroll
    for (int w = 0; w < 8; ++w) total += wsum[w];
    const int padded = (total + 127) & ~127;
    for (int j = total + tid; j < padded; j += 256) {
        g_idx[b * SS + j]   = 0;
        g_amask[b * SS + j] = -1e9f;
    }
    if (tid == 0) g_cnt[b] = padded >> 6;
}

// =============================================================================
// bf16 GEMM core: 128x128x64 CTA tile, 4 warps, warp tile 64x64.
// MODE: 0 = bf16 out (scaled), 1 = bf16 out + add vector (bo + x_cls)
// GATHER: A rows indirected through aidx.
// =============================================================================
#define TBM 128
#define TBN 128
#define TBK 64
#define GPD 72
#define NBUF 3
#define NCH (HID/TBK)
#define GEMM_SMEM (NBUF*(TBM+TBN)*GPD*2)

template<bool GATHER>
__device__ __forceinline__ void gemm_stage(
    const __nv_bfloat16* __restrict__ A, const __nv_bfloat16* __restrict__ W,
    const int* __restrict__ aidx,
    int bm, int bn, int kt, int buf, int tid, uint32_t uBase)
{
    const int k0 = kt * TBK;
    const uint32_t uA = uBase + (uint32_t)buf * TBM * GPD * 2;
    const uint32_t uB = uBase + (uint32_t)(NBUF * TBM + buf * TBN) * GPD * 2;
#pragma unroll
    for (int i = 0; i < 8; ++i) {
        int idx = tid + i * 128;
        int row = idx >> 3, cc = (idx & 7) * 8;
        const __nv_bfloat16* arow = GATHER
            ? A + (size_t)aidx[bm + row] * HID
            : A + (size_t)(bm + row) * HID;
        cp16(uA + (uint32_t)(row * GPD + cc) * 2, arow + k0 + cc);
        cp16(uB + (uint32_t)(row * GPD + cc) * 2,
             W + (size_t)(bn + row) * HID + k0 + cc);
    }
}

__device__ __forceinline__ void gemm_load_frags(
    uint32_t af[4][4], uint32_t bf[4][4],
    uint32_t uA, uint32_t uB, int kk, int wm, int wn, int lane)
{
#pragma unroll
    for (int mt = 0; mt < 4; ++mt) {
        int row = wm + mt * 16 + (lane & 15);
        int col = kk + ((lane >> 4) << 3);
        ldsm_x4(af[mt], uA + (uint32_t)(row * GPD + col) * 2);
    }
#pragma unroll
    for (int np = 0; np < 4; ++np) {
        int row = wn + np * 16 + ((lane & 16) >> 1) + (lane & 7);
        int col = kk + (lane & 8);
        ldsm_x4(bf[np], uB + (uint32_t)(row * GPD + col) * 2);
    }
}

template<int MODE, bool GATHER>
__device__ __forceinline__ void gemm_core(
    const __nv_bfloat16* __restrict__ A, const __nv_bfloat16* __restrict__ W,
    const int* __restrict__ aidx, const float* __restrict__ addv,
    void* __restrict__ Cv, int ldc, float scale, int bm, int bn, uint32_t uBase)
{
    const int tid = threadIdx.x, lane = tid & 31, wid = tid >> 5;
    const int wm = (wid & 1) * 64, wn = (wid >> 1) * 64;
    const int g = lane >> 2, t4 = lane & 3;

    float acc[4][8][4];
#pragma unroll
    for (int mt = 0; mt < 4; ++mt)
#pragma unroll
        for (int nt = 0; nt < 8; ++nt)
#pragma unroll
            for (int i = 0; i < 4; ++i) acc[mt][nt][i] = 0.f;

#pragma unroll
    for (int p = 0; p < 2; ++p) {
        gemm_stage<GATHER>(A, W, aidx, bm, bn, p, p, tid, uBase);
        CP_COMMIT;
    }

    uint32_t af[2][4][4], bf[2][4][4];

    for (int kt = 0; kt < NCH; ++kt) {
        const int buf = kt % NBUF;
        const uint32_t uA = uBase + (uint32_t)buf * TBM * GPD * 2;
        const uint32_t uB = uBase + (uint32_t)(NBUF * TBM + buf * TBN) * GPD * 2;

        CP_WAIT1;
        __syncthreads();

        if (kt + 2 < NCH)
            gemm_stage<GATHER>(A, W, aidx, bm, bn, kt + 2, (kt + 2) % NBUF, tid, uBase);
        CP_COMMIT;

        gemm_load_frags(af[0], bf[0], uA, uB, 0, wm, wn, lane);

#pragma unroll
        for (int ks = 0; ks < 4; ++ks) {
            const int cur = ks & 1;
            if (ks < 3)
                gemm_load_frags(af[cur ^ 1], bf[cur ^ 1], uA, uB,
                                (ks + 1) * 16, wm, wn, lane);
#pragma unroll
            for (int mt = 0; mt < 4; ++mt)
#pragma unroll
                for (int np = 0; np < 4; ++np) {
                    mma_bf16(acc[mt][2 * np],     af[cur][mt], bf[cur][np][0], bf[cur][np][1]);
                    mma_bf16(acc[mt][2 * np + 1], af[cur][mt], bf[cur][np][2], bf[cur][np][3]);
                }
        }
    }

    __nv_bfloat16* C = (__nv_bfloat16*)Cv;
    if (MODE == 0) {
#pragma unroll
        for (int mt = 0; mt < 4; ++mt) {
            int r0 = bm + wm + mt * 16 + g;
#pragma unroll
            for (int nt = 0; nt < 8; ++nt) {
                int c = bn + wn + nt * 8 + 2 * t4;
                *(uint32_t*)(C + (size_t)r0 * ldc + c) =
                    f2bf2(acc[mt][nt][0] * scale, acc[mt][nt][1] * scale);
                *(uint32_t*)(C + (size_t)(r0 + 8) * ldc + c) =
                    f2bf2(acc[mt][nt][2] * scale, acc[mt][nt][3] * scale);
            }
        }
    } else {
        float a0[8], a1[8];
#pragma unroll
        for (int nt = 0; nt < 8; ++nt) {
            int c = bn + wn + nt * 8 + 2 * t4;
            a0[nt] = addv[c];
            a1[nt] = addv[c + 1];
        }
#pragma unroll
        for (int mt = 0; mt < 4; ++mt) {
            int r0 = bm + wm + mt * 16 + g;
#pragma unroll
            for (int nt = 0; nt < 8; ++nt) {
                int c = bn + wn + nt * 8 + 2 * t4;
                *(uint32_t*)(C + (size_t)r0 * ldc + c) =
                    f2bf2(acc[mt][nt][0] + a0[nt], acc[mt][nt][1] + a1[nt]);
                *(uint32_t*)(C + (size_t)(r0 + 8) * ldc + c) =
                    f2bf2(acc[mt][nt][2] + a0[nt], acc[mt][nt][3] + a1[nt]);
            }
        }
    }
}

// fused Q + compacted-KV projection
__global__ __launch_bounds__(128, 2) void gemm_qkv(
    const __nv_bfloat16* __restrict__ x1, const __nv_bfloat16* __restrict__ x2,
    const __nv_bfloat16* __restrict__ Wq, const __nv_bfloat16* __restrict__ Wkv,
    __nv_bfloat16* __restrict__ Cq, __nv_bfloat16* __restrict__ Ckv, float qscale)
{
    extern __shared__ __nv_bfloat16 smg[];
    const uint32_t uBase = (uint32_t)__cvta_generic_to_shared(smg);
    if (blockIdx.x < 8) {
        gemm_core<0, false>(x1, Wq, nullptr, nullptr, Cq, HID, qscale,
                            blockIdx.y * TBM, blockIdx.x * TBN, uBase);
    } else {
        const int b = blockIdx.y >> 3, mtile = blockIdx.y & 7;
        const int rows = g_cnt[b] << 6;
        if (mtile * TBM >= rows) return;
        gemm_core<0, true>(x2 + (size_t)(b * SS) * HID, Wkv,
                           g_idx + b * SS, nullptr,
                           Ckv + (size_t)(b * SS) * 2048, 2 * HID, 1.0f,
                           mtile * TBM, (blockIdx.x - 8) * TBN, uBase);
    }
}

// O projection: bf16 out with fused (+bo +x_cls); per-batch add vector in smem
__global__ __launch_bounds__(128, 2) void gemm_o(
    const __nv_bfloat16* __restrict__ A, const __nv_bfloat16* __restrict__ W,
    const float* __restrict__ bo, const float* __restrict__ x2f,
    __nv_bfloat16* __restrict__ Y)
{
    extern __shared__ __nv_bfloat16 smg[];
    __shared__ float addv[HID];
    const uint32_t uBase = (uint32_t)__cvta_generic_to_shared(smg);
    const int bm = blockIdx.y * TBM;
    const int b  = bm >> 10;
    // build add vector for this batch (bo + x_cls)
    for (int j = threadIdx.x; j < HID; j += 128)
        addv[j] = bo[j] + x2f[(size_t)b * SS * HID + j];
    __syncthreads();
    gemm_core<1, false>(A, W, nullptr, addv, Y, HID, 1.0f,
                        bm, blockIdx.x * TBN, uBase);
}

// =============================================================================
// bf16 flash attention over COMPACTED contiguous K/V rows.  (unchanged)
// =============================================================================
#define ANBUF 3
#define KP 72
#define AKV (64*KP*2)
#define ATT_SMEM (ANBUF*2*AKV + ANBUF*64*4)

__device__ __forceinline__ void attn_stage(
    const __nv_bfloat16* __restrict__ Kb, const __nv_bfloat16* __restrict__ Vb,
    const float* __restrict__ abase, int t0, int buf, int tid,
    uint32_t uK, uint32_t uV, float* mskf)
{
#pragma unroll
    for (int i = 0; i < 4; ++i) {
        int idx = tid + i * 128;
        int row = idx >> 3, cc = (idx & 7) * 8;
        cp16(uK + (uint32_t)((buf * 64 + row) * KP + cc) * 2,
             Kb + (size_t)(t0 + row) * 2048 + cc);
        cp16(uV + (uint32_t)((buf * 64 + row) * KP + cc) * 2,
             Vb + (size_t)(t0 + row) * 2048 + cc);
    }
    if (tid < 64) mskf[buf * 64 + tid] = abase[t0 + tid];
}

__global__ __launch_bounds__(128, 2) void attn_bf16(
    const __nv_bfloat16* __restrict__ Q, const __nv_bfloat16* __restrict__ KVg,
    __nv_bfloat16* __restrict__ O)
{
    extern __shared__ char sma[];
    const uint32_t uK = (uint32_t)__cvta_generic_to_shared(sma);
    const uint32_t uV = uK + ANBUF * AKV;
    float* mskf = (float*)(sma + 2 * ANBUF * AKV);

    const int m0 = blockIdx.x * 128;
    const int h  = blockIdx.y, b = blockIdx.z;
    const int tid = threadIdx.x, lane = tid & 31, wid = tid >> 5;
    const int g = lane >> 2, t4 = lane & 3;

    const int ntiles = g_cnt[b];
    const float* abase = g_amask + b * SS;

    uint32_t qa[4][2][4];
    const __nv_bfloat16* Qb = Q + (size_t)(b * SS + m0 + wid * 32) * HID + h * HD;
#pragma unroll
    for (int kc = 0; kc < 4; ++kc) {
        int k0 = kc * 16 + t4 * 2;
#pragma unroll
        for (int mt = 0; mt < 2; ++mt) {
            const __nv_bfloat16* Qm = Qb + (size_t)(mt * 16) * HID;
            qa[kc][mt][0] = *(const uint32_t*)(Qm + (size_t)g * HID + k0);
            qa[kc][mt][1] = *(const uint32_t*)(Qm + (size_t)(g + 8) * HID + k0);
            qa[kc][mt][2] = *(const uint32_t*)(Qm + (size_t)g * HID + k0 + 8);
            qa[kc][mt][3] = *(const uint32_t*)(Qm + (size_t)(g + 8) * HID + k0 + 8);
        }
    }

    float oacc[2][8][4];
#pragma unroll
    for (int mt = 0; mt < 2; ++mt)
#pragma unroll
        for (int nt = 0; nt < 8; ++nt)
#pragma unroll
            for (int i = 0; i < 4; ++i) oacc[mt][nt][i] = 0.f;
    float lp[2][2] = {{0.f, 0.f}, {0.f, 0.f}};

    const __nv_bfloat16* Kb = KVg + (size_t)(b * SS) * 2048 + h * HD;
    const __nv_bfloat16* Vb = Kb + 1024;

    for (int p = 0; p < 2 && p < ntiles; ++p) {
        attn_stage(Kb, Vb, abase, p * 64, p, tid, uK, uV, mskf);
        CP_COMMIT;
    }

    for (int t = 0; t < ntiles; ++t) {
        const int buf = t % ANBUF;
        CP_WAIT1;
        __syncthreads();

        if (t + 2 < ntiles)
            attn_stage(Kb, Vb, abase, (t + 2) * 64, (t + 2) % ANBUF,
                       tid, uK, uV, mskf);
        CP_COMMIT;

        float sacc[2][8][4];
#pragma unroll
        for (int mt = 0; mt < 2; ++mt)
#pragma unroll
            for (int nt = 0; nt < 8; ++nt)
#pragma unroll
                for (int i = 0; i < 4; ++i) sacc[mt][nt][i] = 0.f;
#pragma unroll
        for (int ks = 0; ks < 4; ++ks) {
            const int kk = ks * 16;
#pragma unroll
            for (int np = 0; np < 4; ++np) {
                int row = buf * 64 + np * 16 + ((lane & 16) >> 1) + (lane & 7);
                int col = kk + (lane & 8);
                uint32_t bfr[4];
                ldsm_x4(bfr, uK + (uint32_t)(row * KP + col) * 2);
#pragma unroll
                for (int mt = 0; mt < 2; ++mt) {
                    mma_bf16(sacc[mt][2 * np],     qa[ks][mt], bfr[0], bfr[1]);
                    mma_bf16(sacc[mt][2 * np + 1], qa[ks][mt], bfr[2], bfr[3]);
                }
            }
        }

#pragma unroll
        for (int mt = 0; mt < 2; ++mt)
#pragma unroll
            for (int nt = 0; nt < 8; ++nt) {
                int c = nt * 8 + 2 * t4;
                float a0 = mskf[buf * 64 + c], a1 = mskf[buf * 64 + c + 1];
                sacc[mt][nt][0] = ex2f(sacc[mt][nt][0] + a0);
                sacc[mt][nt][1] = ex2f(sacc[mt][nt][1] + a1);
                sacc[mt][nt][2] = ex2f(sacc[mt][nt][2] + a0);
                sacc[mt][nt][3] = ex2f(sacc[mt][nt][3] + a1);
                lp[mt][0] += sacc[mt][nt][0] + sacc[mt][nt][1];
                lp[mt][1] += sacc[mt][nt][2] + sacc[mt][nt][3];
            }

#pragma unroll
        for (int kt = 0; kt < 4; ++kt) {
            uint32_t pf[2][4];
#pragma unroll
            for (int mt = 0; mt < 2; ++mt) {
                pf[mt][0] = f2bf2(sacc[mt][2 * kt][0],     sacc[mt][2 * kt][1]);
                pf[mt][1] = f2bf2(sacc[mt][2 * kt][2],     sacc[mt][2 * kt][3]);
                pf[mt][2] = f2bf2(sacc[mt][2 * kt + 1][0], sacc[mt][2 * kt + 1][1]);
                pf[mt][3] = f2bf2(sacc[mt][2 * kt + 1][2], sacc[mt][2 * kt + 1][3]);
            }
#pragma unroll
            for (int dtp = 0; dtp < 4; ++dtp) {
                int row = buf * 64 + kt * 16 + (lane & 15);
                int col = dtp * 16 + ((lane >> 4) & 1) * 8;
                uint32_t bfr[4];
                ldsm_x4t(bfr, uV + (uint32_t)(row * KP + col) * 2);
#pragma unroll
                for (int mt = 0; mt < 2; ++mt) {
                    mma_bf16(oacc[mt][2 * dtp],     pf[mt], bfr[0], bfr[1]);
                    mma_bf16(oacc[mt][2 * dtp + 1], pf[mt], bfr[2], bfr[3]);
                }
            }
        }
    }

#pragma unroll
    for (int mt = 0; mt < 2; ++mt)
#pragma unroll
        for (int rr = 0; rr < 2; ++rr) {
            lp[mt][rr] += __shfl_xor_sync(0xffffffffu, lp[mt][rr], 1);
            lp[mt][rr] += __shfl_xor_sync(0xffffffffu, lp[mt][rr], 2);
        }

    __nv_bfloat16* Ob = O + (size_t)(b * SS + m0 + wid * 32) * HID + h * HD;
#pragma unroll
    for (int mt = 0; mt < 2; ++mt) {
        const float inv0 = 1.0f / lp[mt][0], inv1 = 1.0f / lp[mt][1];
#pragma unroll
        for (int dt = 0; dt < 8; ++dt) {
            int c = dt * 8 + 2 * t4;
            *(uint32_t*)(Ob + (size_t)(mt * 16 + g) * HID + c) =
                f2bf2(oacc[mt][dt][0] * inv0, oacc[mt][dt][1] * inv0);
            *(uint32_t*)(Ob + (size_t)(mt * 16 + g + 8) * HID + c) =
                f2bf2(oacc[mt][dt][2] * inv1, oacc[mt][dt][3] * inv1);
        }
    }
}

// =============================================================================
// LayerNorm + partial mean over bf16 y (add already fused into gemm_o)
// =============================================================================
__global__ __launch_bounds__(256) void ln_mean_kernel(
    const __nv_bfloat16* __restrict__ Y,
    const float* __restrict__ gamma, const float* __restrict__ beta,
    float* __restrict__ part)
{
    const int blk = blockIdx.x;
    const int b = blk >> 6, slice = blk & 63;
    const int tid = threadIdx.x, lane = tid & 31, wid = tid >> 5;

    __shared__ float smu[16], sinv[16];
    const int row0 = (b << 10) + (slice << 4);

#pragma unroll
    for (int rr = 0; rr < 2; ++rr) {
        const int t = wid + rr * 8;
        const __nv_bfloat162* y2 = (const __nv_bfloat162*)(Y + (size_t)(row0 + t) * HID);
        float s = 0.f, ss = 0.f;
#pragma unroll
        for (int k = 0; k < 16; ++k) {
            float2 f = __bfloat1622float2(y2[lane + k * 32]);
            s += f.x + f.y;
            ss += f.x * f.x + f.y * f.y;
        }
#pragma unroll
        for (int off = 16; off; off >>= 1) {
            s  += __shfl_xor_sync(0xffffffffu, s,  off);
            ss += __shfl_xor_sync(0xffffffffu, ss, off);
        }
        if (lane == 0) {
            float mu  = s * (1.0f / HID);
            float var = ss * (1.0f / HID) - mu * mu;
            smu[t]  = mu;
            sinv[t] = rsqrtf(var + 1e-5f);
        }
    }
    __syncthreads();

    float gam[4], bet[4], acc[4] = {0.f, 0.f, 0.f, 0.f};
#pragma unroll
    for (int it = 0; it < 4; ++it) {
        int j = tid + it * 256;
        gam[it] = gamma[j];
        bet[it] = beta[j];
    }
    for (int t = 0; t < 16; ++t) {
        const __nv_bfloat16* y = Y + (size_t)(row0 + t) * HID;
        const float mu = smu[t], inv = sinv[t];
#pragma unroll
        for (int it = 0; it < 4; ++it) {
            float v = __bfloat162float(y[tid + it * 256]);
            acc[it] += (v - mu) * inv * gam[it] + bet[it];
        }
    }
#pragma unroll
    for (int it = 0; it < 4; ++it)
        part[(size_t)slice * (BB * HID) + (b << 10) + tid + it * 256] = acc[it];
}

__global__ __launch_bounds__(256) void final_mean_kernel(
    const float* __restrict__ part, float* __restrict__ out)
{
    const int idx = blockIdx.x * 256 + threadIdx.x;
    float s = 0.f;
#pragma unroll
    for (int p = 0; p < 64; ++p) s += part[(size_t)p * (BB * HID) + idx];
    out[idx] = s * (1.0f / SS);
}

// =============================================================================
// launch
// =============================================================================
extern "C" void kernel_launch(void* const* d_in, const int* in_sizes, int n_in,
                              void* d_out, int out_size)
{
    const float* x1    = (const float*)d_in[0];
    const float* x2    = (const float*)d_in[1];
    const int*   mask  = (const int*)  d_in[2];
    const float* Wq    = (const float*)d_in[3];
    const float* Wk    = (const float*)d_in[4];
    const float* Wv    = (const float*)d_in[5];
    const float* Wo    = (const float*)d_in[6];
    const float* bo    = (const float*)d_in[7];
    const float* gamma = (const float*)d_in[8];
    const float* beta  = (const float*)d_in[9];
    float* out = (float*)d_out;

    void *bx1, *bx2, *bw, *bq, *bkv, *bao, *by, *part;
    cudaGetSymbolAddress(&bx1, g_bx1);
    cudaGetSymbolAddress(&bx2, g_bx2);
    cudaGetSymbolAddress(&bw,  g_bw);
    cudaGetSymbolAddress(&bq,  g_bq);
    cudaGetSymbolAddress(&bkv, g_bkv);
    cudaGetSymbolAddress(&bao, g_bao);
    cudaGetSymbolAddress(&by,  g_by);
    cudaGetSymbolAddress(&part, g_part);

    __nv_bfloat16* bW = (__nv_bfloat16*)bw;

    cudaFuncSetAttribute(gemm_qkv,
        cudaFuncAttributeMaxDynamicSharedMemorySize, GEMM_SMEM);
    cudaFuncSetAttribute(gemm_o,
        cudaFuncAttributeMaxDynamicSharedMemorySize, GEMM_SMEM);
    cudaFuncSetAttribute(attn_bf16,
        cudaFuncAttributeMaxDynamicSharedMemorySize, ATT_SMEM);

    // mask compaction + merged conversions
    compact_mask<<<BB, 256>>>(mask);
    dim3 gc(MTOT * HID / 1024, 6);
    conv_all<<<gc, 256>>>(x1, x2, Wq, Wk, Wv, Wo,
                          (__nv_bfloat16*)bx1, (__nv_bfloat16*)bx2, bW);

    const float QSCALE = 0.125f * 1.4426950408889634f;

    dim3 gqkv(8 + 16, MTOT / TBM);           // (24, 32)
    gemm_qkv<<<gqkv, 128, GEMM_SMEM>>>((const __nv_bfloat16*)bx1,
                                       (const __nv_bfloat16*)bx2,
                                       bW, bW + (size_t)HID * HID,
                                       (__nv_bfloat16*)bq, (__nv_bfloat16*)bkv,
                                       QSCALE);

    dim3 ga(SS / 128, NH, BB);               // (8, 16, 4)
    attn_bf16<<<ga, 128, ATT_SMEM>>>((const __nv_bfloat16*)bq,
                                     (const __nv_bfloat16*)bkv,
                                     (__nv_bfloat16*)bao);

    dim3 go(HID / TBN, MTOT / TBM);          // (8, 32)
    gemm_o<<<go, 128, GEMM_SMEM>>>((const __nv_bfloat16*)bao,
                                   bW + (size_t)3 * HID * HID,
                                   bo, x2, (__nv_bfloat16*)by);

    ln_mean_kernel<<<BB * 64, 256>>>((const __nv_bfloat16*)by, gamma, beta,
                                     (float*)part);
    final_mean_kernel<<<BB * HID / 256, 256>>>((const float*)part, out);
}

// round 17
// speedup vs baseline: 1.0246x; 1.0246x over previous
#include <cuda_runtime.h>
#include <cuda_bf16.h>
#include <cstdint>

#define BB   4
#define SS   1024
#define HID  1024
#define NH   16
#define HD   64
#define MTOT (BB*SS)

// ---------------- scratch ----------------
__device__ __nv_bfloat16 g_bx1[MTOT*HID];
__device__ __nv_bfloat16 g_bx2[MTOT*HID];
__device__ __nv_bfloat16 g_bw [4*HID*HID];      // Wq,Wk,Wv,Wo (bf16, contiguous)
__device__ __nv_bfloat16 g_bq [MTOT*HID];
__device__ __nv_bfloat16 g_bkv[MTOT*2*HID];     // COMPACTED [K | V] rows, stride 2048
__device__ __nv_bfloat16 g_bao[MTOT*HID];
__device__ __nv_bfloat16 g_by [MTOT*HID];       // y = out + bo + x_cls (bf16)
__device__ float         g_part[64*BB*HID];
__device__ int           g_idx [BB*SS];
__device__ float         g_amask[BB*SS];
__device__ int           g_cnt [BB];

// ---------------- helpers ----------------
__device__ __forceinline__ uint32_t f2bf2(float lo, float hi){
    uint32_t r; asm("cvt.rn.bf16x2.f32 %0, %1, %2;" : "=r"(r) : "f"(hi), "f"(lo));
    return r;
}
__device__ __forceinline__ float ex2f(float x){
    float y; asm("ex2.approx.ftz.f32 %0, %1;" : "=f"(y) : "f"(x)); return y;
}
__device__ __forceinline__ void mma_bf16(float* d,
    const uint32_t* a, uint32_t b0, uint32_t b1)
{
    asm volatile(
        "mma.sync.aligned.m16n8k16.row.col.f32.bf16.bf16.f32 "
        "{%0,%1,%2,%3}, {%4,%5,%6,%7}, {%8,%9}, {%0,%1,%2,%3};"
        : "+f"(d[0]), "+f"(d[1]), "+f"(d[2]), "+f"(d[3])
        : "r"(a[0]), "r"(a[1]), "r"(a[2]), "r"(a[3]), "r"(b0), "r"(b1));
}
__device__ __forceinline__ void ldsm_x4(uint32_t* r, uint32_t a){
    asm volatile("ldmatrix.sync.aligned.m8n8.x4.shared.b16 {%0,%1,%2,%3}, [%4];"
                 : "=r"(r[0]), "=r"(r[1]), "=r"(r[2]), "=r"(r[3]) : "r"(a));
}
__device__ __forceinline__ void ldsm_x4t(uint32_t* r, uint32_t a){
    asm volatile("ldmatrix.sync.aligned.m8n8.x4.trans.shared.b16 {%0,%1,%2,%3}, [%4];"
                 : "=r"(r[0]), "=r"(r[1]), "=r"(r[2]), "=r"(r[3]) : "r"(a));
}
__device__ __forceinline__ void cp16(uint32_t dst, const void* src){
    asm volatile("cp.async.cg.shared.global [%0], [%1], 16;" :: "r"(dst), "l"(src));
}
#define CP_COMMIT asm volatile("cp.async.commit_group;" ::: "memory")
#define CP_WAIT1  asm volatile("cp.async.wait_group 1;" ::: "memory")

// =============================================================================
// merged conversions: grid (1024, 12), no dead blocks.
// seg 0-3: x1 quarters; seg 4-7: x2 quarters; seg 8-11: Wq..Wo.
// =============================================================================
__global__ __launch_bounds__(256) void conv_all(
    const float* __restrict__ x1, const float* __restrict__ x2,
    const float* __restrict__ w0, const float* __restrict__ w1,
    const float* __restrict__ w2, const float* __restrict__ w3,
    __nv_bfloat16* __restrict__ dx1, __nv_bfloat16* __restrict__ dx2,
    __nv_bfloat16* __restrict__ dw)
{
    const int seg = blockIdx.y;
    const size_t SEG = (size_t)HID * HID;   // 1M elements per segment
    const float* s;
    __nv_bfloat16* d;
    if (seg < 4)      { s = x1 + seg * SEG;       d = dx1 + seg * SEG; }
    else if (seg < 8) { s = x2 + (seg - 4) * SEG; d = dx2 + (seg - 4) * SEG; }
    else {
        s = seg == 8 ? w0 : seg == 9 ? w1 : seg == 10 ? w2 : w3;
        d = dw + (size_t)(seg - 8) * SEG;
    }
    int i = (blockIdx.x * 256 + threadIdx.x) * 4;
    float4 v = *(const float4*)(s + i);
    *(uint2*)(d + i) = make_uint2(f2bf2(v.x, v.y), f2bf2(v.z, v.w));
}

// =============================================================================
// mask compaction: kept key indices per batch, padded to 128-multiple.
// =============================================================================
__global__ __launch_bounds__(256) void compact_mask(const int* __restrict__ mask)
{
    const int b = blockIdx.x;
    const int tid = threadIdx.x, lane = tid & 31, wid = tid >> 5;
    __shared__ int wsum[8];

    int m[4], cnt = 0;
    const int base = b * SS + tid * 4;
#pragma unroll
    for (int i = 0; i < 4; ++i) { m[i] = mask[base + i]; cnt += (m[i] != 0); }

    int pre = cnt;
#pragma unroll
    for (int off = 1; off < 32; off <<= 1) {
        int v = __shfl_up_sync(0xffffffffu, pre, off);
        if (lane >= off) pre += v;
    }
    if (lane == 31) wsum[wid] = pre;
    __syncthreads();

    int wbase = 0;
#pragma unroll
    for (int w = 0; w < 8; ++w) if (w < wid) wbase += wsum[w];
    int pos = wbase + pre - cnt;

#pragma unroll
    for (int i = 0; i < 4; ++i) {
        if (m[i]) {
            g_idx[b * SS + pos]   = tid * 4 + i;
            g_amask[b * SS + pos] = 0.f;
            ++pos;
        }
    }

    int total = 0;
#pragma unroll
    for (int w = 0; w < 8; ++w) total += wsum[w];
    const int padded = (total + 127) & ~127;
    for (int j = total + tid; j < padded; j += 256) {
        g_idx[b * SS + j]   = 0;
        g_amask[b * SS + j] = -1e9f;
    }
    if (tid == 0) g_cnt[b] = padded >> 6;
}

// =============================================================================
// bf16 GEMM core: 128x128x64 CTA tile, 4 warps, warp tile 64x64.
// MODE: 0 = bf16 out (scaled), 1 = bf16 out + add vector (bo + x_cls)
// GATHER: A rows indirected through aidx.
// =============================================================================
#define TBM 128
#define TBN 128
#define TBK 64
#define GPD 72
#define NBUF 3
#define NCH (HID/TBK)
#define GEMM_SMEM (NBUF*(TBM+TBN)*GPD*2)

template<bool GATHER>
__device__ __forceinline__ void gemm_stage(
    const __nv_bfloat16* __restrict__ A, const __nv_bfloat16* __restrict__ W,
    const int* __restrict__ aidx,
    int bm, int bn, int kt, int buf, int tid, uint32_t uBase)
{
    const int k0 = kt * TBK;
    const uint32_t uA = uBase + (uint32_t)buf * TBM * GPD * 2;
    const uint32_t uB = uBase + (uint32_t)(NBUF * TBM + buf * TBN) * GPD * 2;
#pragma unroll
    for (int i = 0; i < 8; ++i) {
        int idx = tid + i * 128;
        int row = idx >> 3, cc = (idx & 7) * 8;
        const __nv_bfloat16* arow = GATHER
            ? A + (size_t)aidx[bm + row] * HID
            : A + (size_t)(bm + row) * HID;
        cp16(uA + (uint32_t)(row * GPD + cc) * 2, arow + k0 + cc);
        cp16(uB + (uint32_t)(row * GPD + cc) * 2,
             W + (size_t)(bn + row) * HID + k0 + cc);
    }
}

__device__ __forceinline__ void gemm_load_frags(
    uint32_t af[4][4], uint32_t bf[4][4],
    uint32_t uA, uint32_t uB, int kk, int wm, int wn, int lane)
{
#pragma unroll
    for (int mt = 0; mt < 4; ++mt) {
        int row = wm + mt * 16 + (lane & 15);
        int col = kk + ((lane >> 4) << 3);
        ldsm_x4(af[mt], uA + (uint32_t)(row * GPD + col) * 2);
    }
#pragma unroll
    for (int np = 0; np < 4; ++np) {
        int row = wn + np * 16 + ((lane & 16) >> 1) + (lane & 7);
        int col = kk + (lane & 8);
        ldsm_x4(bf[np], uB + (uint32_t)(row * GPD + col) * 2);
    }
}

template<int MODE, bool GATHER>
__device__ __forceinline__ void gemm_core(
    const __nv_bfloat16* __restrict__ A, const __nv_bfloat16* __restrict__ W,
    const int* __restrict__ aidx, const float* __restrict__ addv,
    void* __restrict__ Cv, int ldc, float scale, int bm, int bn, uint32_t uBase)
{
    const int tid = threadIdx.x, lane = tid & 31, wid = tid >> 5;
    const int wm = (wid & 1) * 64, wn = (wid >> 1) * 64;
    const int g = lane >> 2, t4 = lane & 3;

    float acc[4][8][4];
#pragma unroll
    for (int mt = 0; mt < 4; ++mt)
#pragma unroll
        for (int nt = 0; nt < 8; ++nt)
#pragma unroll
            for (int i = 0; i < 4; ++i) acc[mt][nt][i] = 0.f;

#pragma unroll
    for (int p = 0; p < 2; ++p) {
        gemm_stage<GATHER>(A, W, aidx, bm, bn, p, p, tid, uBase);
        CP_COMMIT;
    }

    uint32_t af[2][4][4], bf[2][4][4];

    for (int kt = 0; kt < NCH; ++kt) {
        const int buf = kt % NBUF;
        const uint32_t uA = uBase + (uint32_t)buf * TBM * GPD * 2;
        const uint32_t uB = uBase + (uint32_t)(NBUF * TBM + buf * TBN) * GPD * 2;

        CP_WAIT1;
        __syncthreads();

        if (kt + 2 < NCH)
            gemm_stage<GATHER>(A, W, aidx, bm, bn, kt + 2, (kt + 2) % NBUF, tid, uBase);
        CP_COMMIT;

        gemm_load_frags(af[0], bf[0], uA, uB, 0, wm, wn, lane);

#pragma unroll
        for (int ks = 0; ks < 4; ++ks) {
            const int cur = ks & 1;
            if (ks < 3)
                gemm_load_frags(af[cur ^ 1], bf[cur ^ 1], uA, uB,
                                (ks + 1) * 16, wm, wn, lane);
#pragma unroll
            for (int mt = 0; mt < 4; ++mt)
#pragma unroll
                for (int np = 0; np < 4; ++np) {
                    mma_bf16(acc[mt][2 * np],     af[cur][mt], bf[cur][np][0], bf[cur][np][1]);
                    mma_bf16(acc[mt][2 * np + 1], af[cur][mt], bf[cur][np][2], bf[cur][np][3]);
                }
        }
    }

    __nv_bfloat16* C = (__nv_bfloat16*)Cv;
    if (MODE == 0) {
#pragma unroll
        for (int mt = 0; mt < 4; ++mt) {
            int r0 = bm + wm + mt * 16 + g;
#pragma unroll
            for (int nt = 0; nt < 8; ++nt) {
                int c = bn + wn + nt * 8 + 2 * t4;
                *(uint32_t*)(C + (size_t)r0 * ldc + c) =
                    f2bf2(acc[mt][nt][0] * scale, acc[mt][nt][1] * scale);
                *(uint32_t*)(C + (size_t)(r0 + 8) * ldc + c) =
                    f2bf2(acc[mt][nt][2] * scale, acc[mt][nt][3] * scale);
            }
        }
    } else {
        float a0[8], a1[8];
#pragma unroll
        for (int nt = 0; nt < 8; ++nt) {
            int c = bn + wn + nt * 8 + 2 * t4;
            a0[nt] = addv[c];
            a1[nt] = addv[c + 1];
        }
#pragma unroll
        for (int mt = 0; mt < 4; ++mt) {
            int r0 = bm + wm + mt * 16 + g;
#pragma unroll
            for (int nt = 0; nt < 8; ++nt) {
                int c = bn + wn + nt * 8 + 2 * t4;
                *(uint32_t*)(C + (size_t)r0 * ldc + c) =
                    f2bf2(acc[mt][nt][0] + a0[nt], acc[mt][nt][1] + a1[nt]);
                *(uint32_t*)(C + (size_t)(r0 + 8) * ldc + c) =
                    f2bf2(acc[mt][nt][2] + a0[nt], acc[mt][nt][3] + a1[nt]);
            }
        }
    }
}

// fused Q + compacted-KV projection
__global__ __launch_bounds__(128, 2) void gemm_qkv(
    const __nv_bfloat16* __restrict__ x1, const __nv_bfloat16* __restrict__ x2,
    const __nv_bfloat16* __restrict__ Wq, const __nv_bfloat16* __restrict__ Wkv,
    __nv_bfloat16* __restrict__ Cq, __nv_bfloat16* __restrict__ Ckv, float qscale)
{
    extern __shared__ __nv_bfloat16 smg[];
    const uint32_t uBase = (uint32_t)__cvta_generic_to_shared(smg);
    if (blockIdx.x < 8) {
        gemm_core<0, false>(x1, Wq, nullptr, nullptr, Cq, HID, qscale,
                            blockIdx.y * TBM, blockIdx.x * TBN, uBase);
    } else {
        const int b = blockIdx.y >> 3, mtile = blockIdx.y & 7;
        const int rows = g_cnt[b] << 6;
        if (mtile * TBM >= rows) return;
        gemm_core<0, true>(x2 + (size_t)(b * SS) * HID, Wkv,
                           g_idx + b * SS, nullptr,
                           Ckv + (size_t)(b * SS) * 2048, 2 * HID, 1.0f,
                           mtile * TBM, (blockIdx.x - 8) * TBN, uBase);
    }
}

// O projection: bf16 out with fused (+bo +x_cls); per-batch add vector in smem
__global__ __launch_bounds__(128, 2) void gemm_o(
    const __nv_bfloat16* __restrict__ A, const __nv_bfloat16* __restrict__ W,
    const float* __restrict__ bo, const float* __restrict__ x2f,
    __nv_bfloat16* __restrict__ Y)
{
    extern __shared__ __nv_bfloat16 smg[];
    __shared__ float addv[HID];
    const uint32_t uBase = (uint32_t)__cvta_generic_to_shared(smg);
    const int bm = blockIdx.y * TBM;
    const int b  = bm >> 10;
    for (int j = threadIdx.x; j < HID; j += 128)
        addv[j] = bo[j] + x2f[(size_t)b * SS * HID + j];
    __syncthreads();
    gemm_core<1, false>(A, W, nullptr, addv, Y, HID, 1.0f,
                        bm, blockIdx.x * TBN, uBase);
}

// =============================================================================
// bf16 flash attention over COMPACTED contiguous K/V rows.
// =============================================================================
#define ANBUF 3
#define KP 72
#define AKV (64*KP*2)
#define ATT_SMEM (ANBUF*2*AKV + ANBUF*64*4)

__device__ __forceinline__ void attn_stage(
    const __nv_bfloat16* __restrict__ Kb, const __nv_bfloat16* __restrict__ Vb,
    const float* __restrict__ abase, int t0, int buf, int tid,
    uint32_t uK, uint32_t uV, float* mskf)
{
#pragma unroll
    for (int i = 0; i < 4; ++i) {
        int idx = tid + i * 128;
        int row = idx >> 3, cc = (idx & 7) * 8;
        cp16(uK + (uint32_t)((buf * 64 + row) * KP + cc) * 2,
             Kb + (size_t)(t0 + row) * 2048 + cc);
        cp16(uV + (uint32_t)((buf * 64 + row) * KP + cc) * 2,
             Vb + (size_t)(t0 + row) * 2048 + cc);
    }
    if (tid < 64) mskf[buf * 64 + tid] = abase[t0 + tid];
}

__global__ __launch_bounds__(128, 2) void attn_bf16(
    const __nv_bfloat16* __restrict__ Q, const __nv_bfloat16* __restrict__ KVg,
    __nv_bfloat16* __restrict__ O)
{
    extern __shared__ char sma[];
    const uint32_t uK = (uint32_t)__cvta_generic_to_shared(sma);
    const uint32_t uV = uK + ANBUF * AKV;
    float* mskf = (float*)(sma + 2 * ANBUF * AKV);

    const int m0 = blockIdx.x * 128;
    const int h  = blockIdx.y, b = blockIdx.z;
    const int tid = threadIdx.x, lane = tid & 31, wid = tid >> 5;
    const int g = lane >> 2, t4 = lane & 3;

    const int ntiles = g_cnt[b];
    const float* abase = g_amask + b * SS;

    uint32_t qa[4][2][4];
    const __nv_bfloat16* Qb = Q + (size_t)(b * SS + m0 + wid * 32) * HID + h * HD;
#pragma unroll
    for (int kc = 0; kc < 4; ++kc) {
        int k0 = kc * 16 + t4 * 2;
#pragma unroll
        for (int mt = 0; mt < 2; ++mt) {
            const __nv_bfloat16* Qm = Qb + (size_t)(mt * 16) * HID;
            qa[kc][mt][0] = *(const uint32_t*)(Qm + (size_t)g * HID + k0);
            qa[kc][mt][1] = *(const uint32_t*)(Qm + (size_t)(g + 8) * HID + k0);
            qa[kc][mt][2] = *(const uint32_t*)(Qm + (size_t)g * HID + k0 + 8);
            qa[kc][mt][3] = *(const uint32_t*)(Qm + (size_t)(g + 8) * HID + k0 + 8);
        }
    }

    float oacc[2][8][4];
#pragma unroll
    for (int mt = 0; mt < 2; ++mt)
#pragma unroll
        for (int nt = 0; nt < 8; ++nt)
#pragma unroll
            for (int i = 0; i < 4; ++i) oacc[mt][nt][i] = 0.f;
    float lp[2][2] = {{0.f, 0.f}, {0.f, 0.f}};

    const __nv_bfloat16* Kb = KVg + (size_t)(b * SS) * 2048 + h * HD;
    const __nv_bfloat16* Vb = Kb + 1024;

    for (int p = 0; p < 2 && p < ntiles; ++p) {
        attn_stage(Kb, Vb, abase, p * 64, p, tid, uK, uV, mskf);
        CP_COMMIT;
    }

    for (int t = 0; t < ntiles; ++t) {
        const int buf = t % ANBUF;
        CP_WAIT1;
        __syncthreads();

        if (t + 2 < ntiles)
            attn_stage(Kb, Vb, abase, (t + 2) * 64, (t + 2) % ANBUF,
                       tid, uK, uV, mskf);
        CP_COMMIT;

        float sacc[2][8][4];
#pragma unroll
        for (int mt = 0; mt < 2; ++mt)
#pragma unroll
            for (int nt = 0; nt < 8; ++nt)
#pragma unroll
                for (int i = 0; i < 4; ++i) sacc[mt][nt][i] = 0.f;
#pragma unroll
        for (int ks = 0; ks < 4; ++ks) {
            const int kk = ks * 16;
#pragma unroll
            for (int np = 0; np < 4; ++np) {
                int row = buf * 64 + np * 16 + ((lane & 16) >> 1) + (lane & 7);
                int col = kk + (lane & 8);
                uint32_t bfr[4];
                ldsm_x4(bfr, uK + (uint32_t)(row * KP + col) * 2);
#pragma unroll
                for (int mt = 0; mt < 2; ++mt) {
                    mma_bf16(sacc[mt][2 * np],     qa[ks][mt], bfr[0], bfr[1]);
                    mma_bf16(sacc[mt][2 * np + 1], qa[ks][mt], bfr[2], bfr[3]);
                }
            }
        }

#pragma unroll
        for (int mt = 0; mt < 2; ++mt)
#pragma unroll
            for (int nt = 0; nt < 8; ++nt) {
                int c = nt * 8 + 2 * t4;
                float a0 = mskf[buf * 64 + c], a1 = mskf[buf * 64 + c + 1];
                sacc[mt][nt][0] = ex2f(sacc[mt][nt][0] + a0);
                sacc[mt][nt][1] = ex2f(sacc[mt][nt][1] + a1);
                sacc[mt][nt][2] = ex2f(sacc[mt][nt][2] + a0);
                sacc[mt][nt][3] = ex2f(sacc[mt][nt][3] + a1);
                lp[mt][0] += sacc[mt][nt][0] + sacc[mt][nt][1];
                lp[mt][1] += sacc[mt][nt][2] + sacc[mt][nt][3];
            }

#pragma unroll
        for (int kt = 0; kt < 4; ++kt) {
            uint32_t pf[2][4];
#pragma unroll
            for (int mt = 0; mt < 2; ++mt) {
                pf[mt][0] = f2bf2(sacc[mt][2 * kt][0],     sacc[mt][2 * kt][1]);
                pf[mt][1] = f2bf2(sacc[mt][2 * kt][2],     sacc[mt][2 * kt][3]);
                pf[mt][2] = f2bf2(sacc[mt][2 * kt + 1][0], sacc[mt][2 * kt + 1][1]);
                pf[mt][3] = f2bf2(sacc[mt][2 * kt + 1][2], sacc[mt][2 * kt + 1][3]);
            }
#pragma unroll
            for (int dtp = 0; dtp < 4; ++dtp) {
                int row = buf * 64 + kt * 16 + (lane & 15);
                int col = dtp * 16 + ((lane >> 4) & 1) * 8;
                uint32_t bfr[4];
                ldsm_x4t(bfr, uV + (uint32_t)(row * KP + col) * 2);
#pragma unroll
                for (int mt = 0; mt < 2; ++mt) {
                    mma_bf16(oacc[mt][2 * dtp],     pf[mt], bfr[0], bfr[1]);
                    mma_bf16(oacc[mt][2 * dtp + 1], pf[mt], bfr[2], bfr[3]);
                }
            }
        }
    }

#pragma unroll
    for (int mt = 0; mt < 2; ++mt)
#pragma unroll
        for (int rr = 0; rr < 2; ++rr) {
            lp[mt][rr] += __shfl_xor_sync(0xffffffffu, lp[mt][rr], 1);
            lp[mt][rr] += __shfl_xor_sync(0xffffffffu, lp[mt][rr], 2);
        }

    __nv_bfloat16* Ob = O + (size_t)(b * SS + m0 + wid * 32) * HID + h * HD;
#pragma unroll
    for (int mt = 0; mt < 2; ++mt) {
        const float inv0 = 1.0f / lp[mt][0], inv1 = 1.0f / lp[mt][1];
#pragma unroll
        for (int dt = 0; dt < 8; ++dt) {
            int c = dt * 8 + 2 * t4;
            *(uint32_t*)(Ob + (size_t)(mt * 16 + g) * HID + c) =
                f2bf2(oacc[mt][dt][0] * inv0, oacc[mt][dt][1] * inv0);
            *(uint32_t*)(Ob + (size_t)(mt * 16 + g + 8) * HID + c) =
                f2bf2(oacc[mt][dt][2] * inv1, oacc[mt][dt][3] * inv1);
        }
    }
}

// =============================================================================
// LayerNorm + partial mean over bf16 y
// =============================================================================
__global__ __launch_bounds__(256) void ln_mean_kernel(
    const __nv_bfloat16* __restrict__ Y,
    const float* __restrict__ gamma, const float* __restrict__ beta,
    float* __restrict__ part)
{
    const int blk = blockIdx.x;
    const int b = blk >> 6, slice = blk & 63;
    const int tid = threadIdx.x, lane = tid & 31, wid = tid >> 5;

    __shared__ float smu[16], sinv[16];
    const int row0 = (b << 10) + (slice << 4);

#pragma unroll
    for (int rr = 0; rr < 2; ++rr) {
        const int t = wid + rr * 8;
        const __nv_bfloat162* y2 = (const __nv_bfloat162*)(Y + (size_t)(row0 + t) * HID);
        float s = 0.f, ss = 0.f;
#pragma unroll
        for (int k = 0; k < 16; ++k) {
            float2 f = __bfloat1622float2(y2[lane + k * 32]);
            s += f.x + f.y;
            ss += f.x * f.x + f.y * f.y;
        }
#pragma unroll
        for (int off = 16; off; off >>= 1) {
            s  += __shfl_xor_sync(0xffffffffu, s,  off);
            ss += __shfl_xor_sync(0xffffffffu, ss, off);
        }
        if (lane == 0) {
            float mu  = s * (1.0f / HID);
            float var = ss * (1.0f / HID) - mu * mu;
            smu[t]  = mu;
            sinv[t] = rsqrtf(var + 1e-5f);
        }
    }
    __syncthreads();

    float gam[4], bet[4], acc[4] = {0.f, 0.f, 0.f, 0.f};
#pragma unroll
    for (int it = 0; it < 4; ++it) {
        int j = tid + it * 256;
        gam[it] = gamma[j];
        bet[it] = beta[j];
    }
    for (int t = 0; t < 16; ++t) {
        const __nv_bfloat16* y = Y + (size_t)(row0 + t) * HID;
        const float mu = smu[t], inv = sinv[t];
#pragma unroll
        for (int it = 0; it < 4; ++it) {
            float v = __bfloat162float(y[tid + it * 256]);
            acc[it] += (v - mu) * inv * gam[it] + bet[it];
        }
    }
#pragma unroll
    for (int it = 0; it < 4; ++it)
        part[(size_t)slice * (BB * HID) + (b << 10) + tid + it * 256] = acc[it];
}

__global__ __launch_bounds__(256) void final_mean_kernel(
    const float* __restrict__ part, float* __restrict__ out)
{
    const int idx = blockIdx.x * 256 + threadIdx.x;
    float s = 0.f;
#pragma unroll
    for (int p = 0; p < 64; ++p) s += part[(size_t)p * (BB * HID) + idx];
    out[idx] = s * (1.0f / SS);
}

// =============================================================================
// launch
// =============================================================================
extern "C" void kernel_launch(void* const* d_in, const int* in_sizes, int n_in,
                              void* d_out, int out_size)
{
    const float* x1    = (const float*)d_in[0];
    const float* x2    = (const float*)d_in[1];
    const int*   mask  = (const int*)  d_in[2];
    const float* Wq    = (const float*)d_in[3];
    const float* Wk    = (const float*)d_in[4];
    const float* Wv    = (const float*)d_in[5];
    const float* Wo    = (const float*)d_in[6];
    const float* bo    = (const float*)d_in[7];
    const float* gamma = (const float*)d_in[8];
    const float* beta  = (const float*)d_in[9];
    float* out = (float*)d_out;

    void *bx1, *bx2, *bw, *bq, *bkv, *bao, *by, *part;
    cudaGetSymbolAddress(&bx1, g_bx1);
    cudaGetSymbolAddress(&bx2, g_bx2);
    cudaGetSymbolAddress(&bw,  g_bw);
    cudaGetSymbolAddress(&bq,  g_bq);
    cudaGetSymbolAddress(&bkv, g_bkv);
    cudaGetSymbolAddress(&bao, g_bao);
    cudaGetSymbolAddress(&by,  g_by);
    cudaGetSymbolAddress(&part, g_part);

    __nv_bfloat16* bW = (__nv_bfloat16*)bw;

    cudaFuncSetAttribute(gemm_qkv,
        cudaFuncAttributeMaxDynamicSharedMemorySize, GEMM_SMEM);
    cudaFuncSetAttribute(gemm_o,
        cudaFuncAttributeMaxDynamicSharedMemorySize, GEMM_SMEM);
    cudaFuncSetAttribute(attn_bf16,
        cudaFuncAttributeMaxDynamicSharedMemorySize, ATT_SMEM);

    // mask compaction + merged conversions (no dead blocks)
    compact_mask<<<BB, 256>>>(mask);
    dim3 gc(1024, 12);
    conv_all<<<gc, 256>>>(x1, x2, Wq, Wk, Wv, Wo,
                          (__nv_bfloat16*)bx1, (__nv_bfloat16*)bx2, bW);

    const float QSCALE = 0.125f * 1.4426950408889634f;

    dim3 gqkv(8 + 16, MTOT / TBM);           // (24, 32)
    gemm_qkv<<<gqkv, 128, GEMM_SMEM>>>((const __nv_bfloat16*)bx1,
                                       (const __nv_bfloat16*)bx2,
                                       bW, bW + (size_t)HID * HID,
                                       (__nv_bfloat16*)bq, (__nv_bfloat16*)bkv,
                                       QSCALE);

    dim3 ga(SS / 128, NH, BB);               // (8, 16, 4)
    attn_bf16<<<ga, 128, ATT_SMEM>>>((const __nv_bfloat16*)bq,
                                     (const __nv_bfloat16*)bkv,
                                     (__nv_bfloat16*)bao);

    dim3 go(HID / TBN, MTOT / TBM);          // (8, 32)
    gemm_o<<<go, 128, GEMM_SMEM>>>((const __nv_bfloat16*)bao,
                                   bW + (size_t)3 * HID * HID,
                                   bo, x2, (__nv_bfloat16*)by);

    ln_mean_kernel<<<BB * 64, 256>>>((const __nv_bfloat16*)by, gamma, beta,
                                     (float*)part);
    final_mean_kernel<<<BB * HID / 256, 256>>>((const float*)part, out);
}